// round 11
// baseline (speedup 1.0000x reference)
#include <cuda_runtime.h>
#include <math.h>
#include <stdint.h>

#define NB 32
#define NS 4096
#define ND 512
#define NCHUNK 32
#define ROWS_PER_CHUNK (NS / NCHUNK)   // 128
#define T1 128
#define SROWS 4                        // rows per pipeline stage
#define DEPTH 4                        // ring depth
#define BIGV 10000.0f

__device__ float g_psum[NB][NCHUNK][ND];
__device__ float g_pmax[NB][NCHUNK][ND];
__device__ float g_pmin[NB][NCHUNK][ND];
__device__ float g_pacc[NB][NCHUNK][ND];
__device__ float g_pm [NB][NCHUNK];
__device__ float g_pl [NB][NCHUNK];
__device__ float g_pcnt[NB][NCHUNK];

__device__ __forceinline__ float dot4(const float4& a, const float4& b) {
    return a.x * b.x + a.y * b.y + a.z * b.z + a.w * b.w;
}
__device__ __forceinline__ void cp_async16(uint32_t dst, const void* src) {
    asm volatile("cp.async.cg.shared.global [%0], [%1], 16;\n" :: "r"(dst), "l"(src));
}
__device__ __forceinline__ void cp_commit() {
    asm volatile("cp.async.commit_group;\n" ::: "memory");
}
template <int N>
__device__ __forceinline__ void cp_wait() {
    asm volatile("cp.async.wait_group %0;\n" :: "n"(N) : "memory");
}

__global__ __launch_bounds__(T1) void pool_pass1(
    const float* __restrict__ x,
    const int* __restrict__ mask,   // 4-byte mask (int32 {0,1} or f32 {0.,1.}): nonzero-bits test exact
    const float* __restrict__ w)
{
    const int chunk = blockIdx.x;
    const int b     = blockIdx.y;
    const int t     = threadIdx.x;
    const int lane  = t & 31;
    const int wid   = t >> 5;

    __shared__ __align__(16) float s_buf[DEPTH][SROWS][ND];   // 32 KB ring
    __shared__ int   s_list[ROWS_PER_CHUNK];
    __shared__ int   s_cnt4[4];
    __shared__ float s_part[SROWS][4];

    const int rowbase = chunk * ROWS_PER_CHUNK;
    const float* xb = x + (size_t)b * NS * ND;

    // ---- block-level compaction of 128 rows
    const int  myrow = wid * 32 + lane;
    const bool a = (mask[(size_t)b * NS + rowbase + myrow] != 0);
    const unsigned bal = __ballot_sync(0xffffffffu, a);
    if (lane == 0) s_cnt4[wid] = __popc(bal);
    __syncthreads();
    int off = 0;
    #pragma unroll
    for (int wv = 0; wv < 4; wv++) if (wv < wid) off += s_cnt4[wv];
    const int ntot = s_cnt4[0] + s_cnt4[1] + s_cnt4[2] + s_cnt4[3];
    if (a) s_list[off + __popc(bal & ((1u << lane) - 1u))] = myrow;
    __syncthreads();

    // thread t exclusively owns columns [c0, c0+4)
    const int c0 = t * 4;
    const float4 w4 = *reinterpret_cast<const float4*>(w + c0);

    float4 vsum = make_float4(0.f, 0.f, 0.f, 0.f);
    float4 vmax = make_float4(-BIGV, -BIGV, -BIGV, -BIGV);
    float4 vmin = make_float4( BIGV,  BIGV,  BIGV,  BIGV);
    float4 vacc = make_float4(0.f, 0.f, 0.f, 0.f);
    float m = -1e30f, l = 0.f;

    const int nstages = (ntot + SROWS - 1) / SROWS;
    const uint32_t sbase =
        (uint32_t)__cvta_generic_to_shared(&s_buf[0][0][0]);

    // stage issuer: each thread copies its own 16B of each row (coalesced gather)
    auto issue = [&](int st) {
        if (st < nstages) {
            const int slot = st & (DEPTH - 1);
            const int r0   = st * SROWS;
            #pragma unroll
            for (int j = 0; j < SROWS; j++) {
                const int r = r0 + j;
                if (r < ntot) {
                    const float* src = xb + (size_t)(rowbase + s_list[r]) * ND + c0;
                    cp_async16(sbase + (uint32_t)(((slot * SROWS + j) * ND + c0) * 4), src);
                }
            }
        }
        cp_commit();   // commit even when empty: keeps group count aligned
    };

    #pragma unroll
    for (int st = 0; st < DEPTH - 1; st++) issue(st);   // prologue: 3 stages in flight

    for (int s = 0; s < nstages; s++) {
        cp_wait<DEPTH - 2>();      // oldest committed stage (s) complete for THIS thread
        __syncthreads();           // make all threads' cp.async data visible
        issue(s + DEPTH - 1);      // refill ring (writes slot (s-1)%4: fully consumed)

        const int slot = s & (DEPTH - 1);
        const int r0   = s * SROWS;

        float4 v[SROWS];
        float  p[SROWS];
        #pragma unroll
        for (int j = 0; j < SROWS; j++)
            v[j] = *reinterpret_cast<const float4*>(&s_buf[slot][j][c0]);
        #pragma unroll
        for (int j = 0; j < SROWS; j++)
            p[j] = dot4(v[j], w4);
        #pragma unroll
        for (int o = 16; o > 0; o >>= 1) {
            #pragma unroll
            for (int j = 0; j < SROWS; j++)
                p[j] += __shfl_xor_sync(0xffffffffu, p[j], o);
        }
        if (lane == 0) {
            #pragma unroll
            for (int j = 0; j < SROWS; j++) s_part[j][wid] = p[j];
        }
        __syncthreads();

        #pragma unroll
        for (int j = 0; j < SROWS; j++) {
            if (r0 + j < ntot) {
                const float sc = s_part[j][0] + s_part[j][1]
                               + s_part[j][2] + s_part[j][3];   // block-uniform
                const float x0 = v[j].x, x1 = v[j].y, x2 = v[j].z, x3 = v[j].w;
                vsum.x += x0; vsum.y += x1; vsum.z += x2; vsum.w += x3;
                vmax.x = fmaxf(vmax.x, x0); vmax.y = fmaxf(vmax.y, x1);
                vmax.z = fmaxf(vmax.z, x2); vmax.w = fmaxf(vmax.w, x3);
                vmin.x = fminf(vmin.x, x0); vmin.y = fminf(vmin.y, x1);
                vmin.z = fminf(vmin.z, x2); vmin.w = fminf(vmin.w, x3);
                if (sc > m) {   // lazy rescale: uniform branch, ~log(n) times per chunk
                    const float sr = __expf(m - sc);
                    l *= sr;
                    vacc.x *= sr; vacc.y *= sr; vacc.z *= sr; vacc.w *= sr;
                    m = sc;
                }
                const float e = __expf(sc - m);
                l += e;
                vacc.x += e * x0; vacc.y += e * x1;
                vacc.z += e * x2; vacc.w += e * x3;
            }
        }
    }

    // ---- per-thread exclusive columns: no cross-warp merge needed
    *reinterpret_cast<float4*>(&g_psum[b][chunk][c0]) = vsum;
    *reinterpret_cast<float4*>(&g_pmax[b][chunk][c0]) = vmax;
    *reinterpret_cast<float4*>(&g_pmin[b][chunk][c0]) = vmin;
    *reinterpret_cast<float4*>(&g_pacc[b][chunk][c0]) = vacc;
    if (t == 0) {
        g_pm[b][chunk]   = m;           // block-uniform
        g_pl[b][chunk]   = l;           // block-uniform
        g_pcnt[b][chunk] = (float)ntot;
    }
}

// pass2 (proven R7 version): grid (NB, 8); block = 64 columns × 8 chunk-slices;
// warp 0 precomputes per-batch normalized softmax weights once.
#define T2 512
#define COLS_PER_BLK 64
#define NSLICE 8
#define CHUNKS_PER_SLICE (NCHUNK / NSLICE)  // 4

__global__ __launch_bounds__(T2) void pool_pass2(float* __restrict__ out)
{
    const int b     = blockIdx.x;
    const int tid   = threadIdx.x;
    const int col   = blockIdx.y * COLS_PER_BLK + (tid & (COLS_PER_BLK - 1));
    const int slice = tid >> 6;

    __shared__ float s_wc[NCHUNK];   // exp(m_c - M) / L
    __shared__ float s_invcnt;
    __shared__ float s_sum[NSLICE][COLS_PER_BLK];
    __shared__ float s_max[NSLICE][COLS_PER_BLK];
    __shared__ float s_min[NSLICE][COLS_PER_BLK];
    __shared__ float s_acc[NSLICE][COLS_PER_BLK];

    if (tid < 32) {
        const float mc = g_pm[b][tid];
        const float lc = g_pl[b][tid];
        const float cc = g_pcnt[b][tid];
        float M = mc;
        #pragma unroll
        for (int o = 16; o > 0; o >>= 1)
            M = fmaxf(M, __shfl_xor_sync(0xffffffffu, M, o));
        const float ec = __expf(mc - M);
        float L = lc * ec, C = cc;
        #pragma unroll
        for (int o = 16; o > 0; o >>= 1) {
            L += __shfl_xor_sync(0xffffffffu, L, o);
            C += __shfl_xor_sync(0xffffffffu, C, o);
        }
        s_wc[tid] = ec / L;
        if (tid == 0) s_invcnt = 1.f / (C + 1e-6f);
    }
    __syncthreads();

    float sum = 0.f, mx = -BIGV, mn = BIGV, acc = 0.f;
    const int cbase = slice * CHUNKS_PER_SLICE;
    #pragma unroll
    for (int ii = 0; ii < CHUNKS_PER_SLICE; ii++) {
        const int c = cbase + ii;
        sum += g_psum[b][c][col];
        mx   = fmaxf(mx, g_pmax[b][c][col]);
        mn   = fminf(mn, g_pmin[b][c][col]);
        acc += g_pacc[b][c][col] * s_wc[c];
    }

    const int lc2 = tid & (COLS_PER_BLK - 1);
    s_sum[slice][lc2] = sum;
    s_max[slice][lc2] = mx;
    s_min[slice][lc2] = mn;
    s_acc[slice][lc2] = acc;
    __syncthreads();

    if (slice == 0) {
        #pragma unroll
        for (int s = 1; s < NSLICE; s++) {
            sum += s_sum[s][lc2];
            mx   = fmaxf(mx, s_max[s][lc2]);
            mn   = fminf(mn, s_min[s][lc2]);
            acc += s_acc[s][lc2];
        }
        float* ob = out + (size_t)b * (4 * ND);
        ob[col]          = sum * s_invcnt;
        ob[ND + col]     = mx;
        ob[2 * ND + col] = mn;
        ob[3 * ND + col] = acc;    // weights already normalized by 1/L
    }
}

extern "C" void kernel_launch(void* const* d_in, const int* in_sizes, int n_in,
                              void* d_out, int out_size)
{
    const float* x  = (const float*)d_in[0];
    const int*   mk = (const int*)d_in[1];
    const float* w  = (const float*)d_in[2];
    float* out      = (float*)d_out;

    dim3 grid1(NCHUNK, NB);   // (32, 32) = 1024 CTAs
    pool_pass1<<<grid1, T1>>>(x, mk, w);
    dim3 grid2(NB, ND / COLS_PER_BLK);   // (32, 8)
    pool_pass2<<<grid2, T2>>>(out);
}